// round 14
// baseline (speedup 1.0000x reference)
#include <cuda_runtime.h>
#include <cuda_fp16.h>
#include <math.h>
#include <stdint.h>

#define BSZ 2
#define SEQ 2048
#define EMB 768
#define NH 12
#define HDIM 64
#define ROWS (BSZ*SEQ)

// fp16 operands. "permuted": within each 16-group, logical (2i,2i+1,2i+8,2i+9)
// stored at phys 4i..4i+3 (so an mma fragment pair is one 8-byte load).
__device__ __half g_xh[ROWS*EMB];          // X, fp16, permuted k-groups
__device__ __half g_w1t[2304*EMB];         // W1^T  [n][k-perm]
__device__ __half g_w2t[1536*EMB];         // W2^T (first 1536 cols; v2 dead)
__device__ __half g_wpt[EMB*EMB];          // Wp^T  [n][k-perm]
__device__ __half g_q1h[BSZ*NH*SEQ*HDIM];  // [B*H][seq][d-perm]
__device__ __half g_k1h[BSZ*NH*SEQ*HDIM];
__device__ __half g_vth[BSZ*NH*SEQ*HDIM];  // V^T [B*H][d][seq-perm]
__device__ __half g_q2h[BSZ*NH*SEQ*HDIM];
__device__ __half g_k2h[BSZ*NH*SEQ*HDIM];
__device__ __half g_atth[ROWS*EMB];        // attention output, fp16
__device__ __half g_xnh[ROWS*EMB];         // rms*nw-scaled, fp16, permuted

// ---------------------------------------------------------------------------
__device__ __forceinline__ float ex2f(float x) {
    float y;
    asm("ex2.approx.f32 %0, %1;" : "=f"(y) : "f"(x));
    return y;
}
__device__ __forceinline__ void mma16(float* c, const uint32_t* a, uint32_t b0, uint32_t b1) {
    asm volatile(
        "mma.sync.aligned.m16n8k16.row.col.f32.f16.f16.f32 "
        "{%0,%1,%2,%3},{%4,%5,%6,%7},{%8,%9},{%0,%1,%2,%3};"
        : "+f"(c[0]), "+f"(c[1]), "+f"(c[2]), "+f"(c[3])
        : "r"(a[0]), "r"(a[1]), "r"(a[2]), "r"(a[3]), "r"(b0), "r"(b1));
}
__device__ __forceinline__ uint32_t pack_h2(float lo, float hi) {
    __half2 h = __float22half2_rn(make_float2(lo, hi));
    return *(uint32_t*)&h;
}
__device__ __forceinline__ float2 unpack_h2(uint32_t u) {
    return __half22float2(*(__half2*)&u);
}
#define CP16(dst_u32, src_ptr) \
    asm volatile("cp.async.cg.shared.global [%0], [%1], 16;" :: "r"(dst_u32), "l"(src_ptr))
#define CPCOMMIT() asm volatile("cp.async.commit_group;")

// 0.125 * log2(e): fold head-dim scale AND exp->exp2 conversion into Q
#define QSCALE 0.18033688011112042f

// ---------------------------------------------------------------------------
// X -> fp16 permuted (row layout preserved). One 16-group per thread.
// ---------------------------------------------------------------------------
__global__ __launch_bounds__(256) void convx_kernel(const float* __restrict__ X)
{
    size_t gidx = (size_t)blockIdx.x * 256 + threadIdx.x;
    const float* src = X + gidx * 16;
    float f[16];
    #pragma unroll
    for (int i = 0; i < 4; i++) {
        float4 v = *(const float4*)(src + 4 * i);
        f[4*i] = v.x; f[4*i+1] = v.y; f[4*i+2] = v.z; f[4*i+3] = v.w;
    }
    uint32_t w8[8];
    #pragma unroll
    for (int i = 0; i < 4; i++) {
        w8[2*i]   = pack_h2(f[2*i],     f[2*i+1]);
        w8[2*i+1] = pack_h2(f[2*i+8],   f[2*i+9]);
    }
    __half* dst = g_xh + gidx * 16;
    *(uint4*)dst       = make_uint4(w8[0], w8[1], w8[2], w8[3]);
    *(uint4*)(dst + 8) = make_uint4(w8[4], w8[5], w8[6], w8[7]);
}

// ---------------------------------------------------------------------------
// W [768 x ncols] f32 (row stride `stride`) -> Wt [ncols][768] fp16 permuted.
// ---------------------------------------------------------------------------
__global__ __launch_bounds__(256) void convw_kernel(const float* __restrict__ W,
                                                    __half* __restrict__ Wt, int stride)
{
    __shared__ float ts[64][65];
    const int nt = blockIdx.x * 64;
    const int kt = blockIdx.y * 64;
    const int tid = threadIdx.x;

    #pragma unroll
    for (int it = 0; it < 4; it++) {
        int idx = tid + it * 256;
        int krow = idx >> 4, nc = (idx & 15) * 4;
        float4 v = *(const float4*)(W + (size_t)(kt + krow) * stride + nt + nc);
        ts[krow][nc] = v.x; ts[krow][nc+1] = v.y; ts[krow][nc+2] = v.z; ts[krow][nc+3] = v.w;
    }
    __syncthreads();

    int n = tid >> 2, grp = tid & 3;
    int kb = grp * 16;
    uint32_t w8[8];
    #pragma unroll
    for (int i = 0; i < 4; i++) {
        w8[2*i]   = pack_h2(ts[kb + 2*i][n],     ts[kb + 2*i + 1][n]);
        w8[2*i+1] = pack_h2(ts[kb + 2*i + 8][n], ts[kb + 2*i + 9][n]);
    }
    __half* dst = Wt + (size_t)(nt + n) * EMB + kt + kb;
    *(uint4*)dst       = make_uint4(w8[0], w8[1], w8[2], w8[3]);
    *(uint4*)(dst + 8) = make_uint4(w8[4], w8[5], w8[6], w8[7]);
}

// ---------------------------------------------------------------------------
// Merged QKV projection GEMM, fp16 m16n8k16, cp.async double-buffered raw
// copies of pre-converted operands. grid (30, 32): bx<18 -> W1t, else W2t.
// ---------------------------------------------------------------------------
__global__ __launch_bounds__(256) void qkv_mma_kernel()
{
    extern __shared__ __align__(16) __half qsm[];
    const int A0 = 0, B0 = 12288;

    const int tid  = threadIdx.x;
    const int lane = tid & 31, warp = tid >> 5;
    const int g = lane >> 2, tig = lane & 3;
    const int wm = warp >> 1, wn = warp & 1;
    const int m0 = blockIdx.y * 128;
    const bool second = blockIdx.x >= 18;
    const int n0 = (second ? blockIdx.x - 18 : blockIdx.x) * 128;

    const __half* Ab = g_xh + (size_t)m0 * EMB;
    const __half* Bb = second ? g_w2t + (size_t)n0 * EMB
                              : g_w1t + (size_t)n0 * EMB;

    const uint32_t smb = (uint32_t)__cvta_generic_to_shared(qsm);

    auto prefetch = [&](int c, int buf) {
        #pragma unroll
        for (int it = 0; it < 2; it++) {
            int idx = tid + it * 256;
            int row = idx >> 2, cc = idx & 3;
            CP16(smb + (uint32_t)(A0 + buf * 6144 + row * 48 + cc * 8) * 2,
                 Ab + (size_t)row * EMB + c * 32 + cc * 8);
            CP16(smb + (uint32_t)(B0 + buf * 6144 + row * 48 + cc * 8) * 2,
                 Bb + (size_t)row * EMB + c * 32 + cc * 8);
        }
        CPCOMMIT();
    };

    prefetch(0, 0);

    float acc[2][8][4] = {};

    const int NC = EMB / 32;   // 24
    for (int c = 0; c < NC; c++) {
        const int cur = c & 1;
        const bool more = (c + 1 < NC);
        if (more) {
            prefetch(c + 1, cur ^ 1);
            asm volatile("cp.async.wait_group 1;");
        } else {
            asm volatile("cp.async.wait_group 0;");
        }
        __syncthreads();

        const int Ac = A0 + cur * 6144;
        const int Bc = B0 + cur * 6144;
        #pragma unroll
        for (int s = 0; s < 2; s++) {
            uint32_t a[2][4];
            #pragma unroll
            for (int mt = 0; mt < 2; mt++) {
                int row = 32 * wm + 16 * mt;
                uint2 u = *(uint2*)&qsm[Ac + (row + g)     * 48 + 16 * s + 4 * tig];
                uint2 v = *(uint2*)&qsm[Ac + (row + g + 8) * 48 + 16 * s + 4 * tig];
                a[mt][0] = u.x; a[mt][1] = v.x; a[mt][2] = u.y; a[mt][3] = v.y;
            }
            #pragma unroll
            for (int t = 0; t < 8; t++) {
                uint2 bb = *(uint2*)&qsm[Bc + (64 * wn + 8 * t + g) * 48 + 16 * s + 4 * tig];
                mma16(acc[0][t], a[0], bb.x, bb.y);
                mma16(acc[1][t], a[1], bb.x, bb.y);
            }
        }
        __syncthreads();
    }

    const int cbase = n0 + 64 * wn;
    const int sel = cbase / EMB;
    const int h = (cbase - sel * EMB) >> 6;
    const int bb = m0 >> 11;

    if (!second && sel == 2) {
        __half* vt = g_vth + (size_t)(bb * NH + h) * HDIM * SEQ;
        #pragma unroll
        for (int mt = 0; mt < 2; mt++) {
            int rb = (m0 & (SEQ - 1)) + 32 * wm + 16 * mt;
            int n1p = rb + 4 * (g >> 1) + (g & 1);
            #pragma unroll
            for (int t = 0; t < 8; t++) {
                int d0 = 8 * t + 2 * tig;
                vt[(size_t)d0 * SEQ + n1p]           = __float2half_rn(acc[mt][t][0]);
                vt[(size_t)(d0 + 1) * SEQ + n1p]     = __float2half_rn(acc[mt][t][1]);
                vt[(size_t)d0 * SEQ + n1p + 2]       = __float2half_rn(acc[mt][t][2]);
                vt[(size_t)(d0 + 1) * SEQ + n1p + 2] = __float2half_rn(acc[mt][t][3]);
            }
        }
    } else {
        __half* dst = second ? (sel == 0 ? g_q2h : g_k2h)
                             : (sel == 0 ? g_q1h : g_k1h);
        const float scl = (sel == 0) ? QSCALE : 1.0f;
        #pragma unroll
        for (int mt = 0; mt < 2; mt++) {
            int n = (m0 + 32 * wm + 16 * mt + g) & (SEQ - 1);
            size_t base = (size_t)(bb * NH + h) * SEQ;
            #pragma unroll
            for (int t = 0; t < 8; t++) {
                int dphys = 16 * (t >> 1) + 4 * tig + 2 * (t & 1);
                *(uint32_t*)&dst[(base + n) * HDIM + dphys] =
                    pack_h2(acc[mt][t][0] * scl, acc[mt][t][1] * scl);
                *(uint32_t*)&dst[(base + n + 8) * HDIM + dphys] =
                    pack_h2(acc[mt][t][2] * scl, acc[mt][t][3] * scl);
            }
        }
    }
}

// ---------------------------------------------------------------------------
// Differential flash attention, fp16 mma, 512 threads, PERSISTENT CTAs.
// grid 148; each CTA loops over 384 (bh, q-tile) jobs. Inner structure = R12:
// 3-stage cp.async pipeline, K1+K2+V one commit group per k-tile, P in regs.
// smem (halfs): Q2 0 (10240), K1 10240 (3x5120), K2 25600, V 40960. 112640 B.
// ---------------------------------------------------------------------------
__global__ __launch_bounds__(512) void diff_attn_fp16(const float* __restrict__ lam1,
                                                      const float* __restrict__ lam2)
{
    extern __shared__ __align__(16) char smraw[];
    __half* smh = (__half*)smraw;
    const int Q2H = 0, K1H = 10240, K2H = 25600, VH = 40960;

    const int tid  = threadIdx.x;
    const int lane = tid & 31, warp = tid >> 5;
    const int g = lane >> 2, tig = lane & 3;
    const int qg = warp & 7, kh = warp >> 3;
    const int r = 16 * qg;
    const uint32_t smb = (uint32_t)__cvta_generic_to_shared(smraw);

    const int QT = SEQ / 128;            // 16 q-tiles per head
    const int NJOBS = QT * BSZ * NH;     // 384
    const int NT = SEQ / 64;             // 32 k-tiles

    for (int job = blockIdx.x; job < NJOBS; job += gridDim.x) {
        const int bh = job / QT;
        const int qt = job - bh * QT;
        const int b = bh / NH, h = bh - b * NH;
        const int q0 = qt * 128;

        const __half* Q1g = g_q1h + ((size_t)bh * SEQ + q0) * HDIM;
        const __half* Q2g = g_q2h + ((size_t)bh * SEQ + q0) * HDIM;
        const __half* K1g = g_k1h + (size_t)bh * SEQ * HDIM;
        const __half* K2g = g_k2h + (size_t)bh * SEQ * HDIM;
        const __half* Vtg = g_vth + (size_t)bh * HDIM * SEQ;

        // Q2 tile -> smem, stride 80 halfs
        #pragma unroll
        for (int it = 0; it < 2; it++) {
            int i = tid + it * 512;
            int row = i >> 3, c = i & 7;
            *(uint4*)&smh[Q2H + row * 80 + c * 8] = *(const uint4*)(Q2g + row * 64 + c * 8);
        }
        // Q1 fragments -> registers
        uint32_t q1f[4][4];
        #pragma unroll
        for (int s = 0; s < 4; s++) {
            uint2 u = *(const uint2*)(Q1g + (r + g)     * 64 + 16 * s + 4 * tig);
            uint2 v = *(const uint2*)(Q1g + (r + g + 8) * 64 + 16 * s + 4 * tig);
            q1f[s][0] = u.x; q1f[s][1] = v.x; q1f[s][2] = u.y; q1f[s][3] = v.y;
        }

        // one commit group per k-tile: K1 + K2 + V
        auto prefetch_all = [&](int kt, int buf) {
            int row = tid >> 3, c = tid & 7;
            CP16(smb + (uint32_t)(K1H + buf * 5120 + row * 80 + c * 8) * 2,
                 K1g + (size_t)kt * 4096 + row * 64 + c * 8);
            CP16(smb + (uint32_t)(K2H + buf * 5120 + row * 80 + c * 8) * 2,
                 K2g + (size_t)kt * 4096 + row * 64 + c * 8);
            CP16(smb + (uint32_t)(VH + buf * 5120 + row * 80 + c * 8) * 2,
                 Vtg + (size_t)row * SEQ + kt * 64 + c * 8);
            CPCOMMIT();
        };

        prefetch_all(0, 0);
        prefetch_all(1, 1);
        prefetch_all(2, 2);

        float o1[8][4] = {}, o2[8][4] = {};
        float l1[2] = {0.f, 0.f}, l2[2] = {0.f, 0.f};

        for (int kt = 0; kt < NT; kt++) {
            const int buf = kt % 3;
            const int pa = NT - kt - 1;
            if (pa >= 2)      asm volatile("cp.async.wait_group 2;");
            else if (pa == 1) asm volatile("cp.async.wait_group 1;");
            else              asm volatile("cp.async.wait_group 0;");
            __syncthreads();

            const int K1c = K1H + buf * 5120;
            const int K2c = K2H + buf * 5120;
            const int Vc  = VH  + buf * 5120;

            uint32_t pa1[2][4], pa2[2][4];
            // ---- merged S phase ----
            {
                float s1[4][4] = {}, s2[4][4] = {};
                #pragma unroll
                for (int s = 0; s < 4; s++) {
                    uint32_t aq[4];
                    uint2 u = *(uint2*)&smh[Q2H + (r + g)     * 80 + 16 * s + 4 * tig];
                    uint2 v = *(uint2*)&smh[Q2H + (r + g + 8) * 80 + 16 * s + 4 * tig];
                    aq[0] = u.x; aq[1] = v.x; aq[2] = u.y; aq[3] = v.y;
                    #pragma unroll
                    for (int t = 0; t < 4; t++) {
                        int kr = 32 * kh + 8 * t + g;
                        uint2 k1 = *(uint2*)&smh[K1c + kr * 80 + 16 * s + 4 * tig];
                        uint2 k2 = *(uint2*)&smh[K2c + kr * 80 + 16 * s + 4 * tig];
                        mma16(s1[t], q1f[s], k1.x, k1.y);
                        mma16(s2[t], aq,     k2.x, k2.y);
                    }
                }
                #pragma unroll
                for (int t = 0; t < 4; t++) {
                    float a0 = ex2f(s1[t][0]);
                    float a1 = ex2f(s1[t][1]);
                    float a2 = ex2f(s1[t][2]);
                    float a3 = ex2f(s1[t][3]);
                    l1[0] += a0 + a1;
                    l1[1] += a2 + a3;
                    pa1[t >> 1][2 * (t & 1)]     = pack_h2(a0, a1);
                    pa1[t >> 1][2 * (t & 1) + 1] = pack_h2(a2, a3);
                    float b0 = ex2f(s2[t][0]);
                    float b1 = ex2f(s2[t][1]);
                    float b2 = ex2f(s2[t][2]);
                    float b3 = ex2f(s2[t][3]);
                    l2[0] += b0 + b1;
                    l2[1] += b2 + b3;
                    pa2[t >> 1][2 * (t & 1)]     = pack_h2(b0, b1);
                    pa2[t >> 1][2 * (t & 1) + 1] = pack_h2(b2, b3);
                }
            }

            // ---- O += P @ V ----
            #pragma unroll
            for (int s2i = 0; s2i < 2; s2i++) {
                #pragma unroll
                for (int t = 0; t < 8; t++) {
                    int vr = 8 * t + g;
                    uint2 vb = *(uint2*)&smh[Vc + vr * 80 + 32 * kh + 16 * s2i + 4 * tig];
                    mma16(o1[t], pa1[s2i], vb.x, vb.y);
                    mma16(o2[t], pa2[s2i], vb.x, vb.y);
                }
            }
            __syncthreads();

            if (kt + 3 < NT) prefetch_all(kt + 3, buf);
        }

        // ---- final reduction across tig lanes (l) and kh warp pairs (l, O) ----
        #pragma unroll
        for (int rr = 0; rr < 2; rr++) {
            l1[rr] += __shfl_xor_sync(0xffffffffu, l1[rr], 1);
            l1[rr] += __shfl_xor_sync(0xffffffffu, l1[rr], 2);
            l2[rr] += __shfl_xor_sync(0xffffffffu, l2[rr], 1);
            l2[rr] += __shfl_xor_sync(0xffffffffu, l2[rr], 2);
        }
        float* ob1 = (float*)smraw;          // 128x68 f32
        float* ob2 = ob1 + 8704;
        float* lbuf = ob2 + 8704;            // 256 f32
        if (kh == 1) {
            #pragma unroll
            for (int t = 0; t < 8; t++) {
                *(float2*)&ob1[(r + g)     * 68 + 8 * t + 2 * tig] = make_float2(o1[t][0], o1[t][1]);
                *(float2*)&ob1[(r + g + 8) * 68 + 8 * t + 2 * tig] = make_float2(o1[t][2], o1[t][3]);
                *(float2*)&ob2[(r + g)     * 68 + 8 * t + 2 * tig] = make_float2(o2[t][0], o2[t][1]);
                *(float2*)&ob2[(r + g + 8) * 68 + 8 * t + 2 * tig] = make_float2(o2[t][2], o2[t][3]);
            }
            if (tig == 0) {
                lbuf[r + g]           = l1[0];
                lbuf[r + g + 8]       = l1[1];
                lbuf[128 + r + g]     = l2[0];
                lbuf[128 + r + g + 8] = l2[1];
            }
        }
        __syncthreads();
        if (kh == 0) {
            const float lam = lam1[h] - lam2[h] + 0.1f;
            const float i10 = 1.f / (l1[0] + lbuf[r + g]);
            const float i11 = 1.f / (l1[1] + lbuf[r + g + 8]);
            const float i20 = 1.f / (l2[0] + lbuf[128 + r + g]);
            const float i21 = 1.f / (l2[1] + lbuf[128 + r + g + 8]);
            const int n = q0 + r + g;
            #pragma unroll
            for (int t = 0; t < 8; t++) {
                const int col = h * HDIM + 8 * t + 2 * tig;
                float2 p10 = *(float2*)&ob1[(r + g)     * 68 + 8 * t + 2 * tig];
                float2 p11 = *(float2*)&ob1[(r + g + 8) * 68 + 8 * t + 2 * tig];
                float2 p20 = *(float2*)&ob2[(r + g)     * 68 + 8 * t + 2 * tig];
                float2 p21 = *(float2*)&ob2[(r + g + 8) * 68 + 8 * t + 2 * tig];
                *(uint32_t*)&g_atth[((size_t)(b * SEQ + n)) * EMB + col] =
                    pack_h2((o1[t][0] + p10.x) * i10 - lam * (o2[t][0] + p20.x) * i20,
                            (o1[t][1] + p10.y) * i10 - lam * (o2[t][1] + p20.y) * i20);
                *(uint32_t*)&g_atth[((size_t)(b * SEQ + n + 8)) * EMB + col] =
                    pack_h2((o1[t][2] + p11.x) * i11 - lam * (o2[t][2] + p21.x) * i21,
                            (o1[t][3] + p11.y) * i11 - lam * (o2[t][3] + p21.y) * i21);
            }
        }
        __syncthreads();   // smem scratch quiesced before next job
    }
}

// ---------------------------------------------------------------------------
// RMSNorm + scale + permute: g_xnh = fp16_perm(g_atth * rms * nw).
// ---------------------------------------------------------------------------
__global__ __launch_bounds__(256) void rms_kernel(const float* __restrict__ nw)
{
    const int lane = threadIdx.x & 31, warp = threadIdx.x >> 5;
    const int row = blockIdx.x * 8 + warp;
    const __half* p = g_atth + (size_t)row * EMB;

    uint4 raw[3];
    float ss = 0.f;
    #pragma unroll
    for (int i = 0; i < 3; i++) {
        raw[i] = *(const uint4*)(p + lane * 8 + i * 256);
        const uint32_t* u = (const uint32_t*)&raw[i];
        #pragma unroll
        for (int m = 0; m < 4; m++) {
            float2 f = unpack_h2(u[m]);
            ss += f.x * f.x + f.y * f.y;
        }
    }
    #pragma unroll
    for (int off = 16; off > 0; off >>= 1)
        ss += __shfl_xor_sync(0xffffffffu, ss, off);
    const float rms = rsqrtf(ss * (1.0f / EMB) + 1e-6f);

    __half* dst = g_xnh + (size_t)row * EMB;
    #pragma unroll
    for (int i = 0; i < 3; i++) {
        int j = lane + i * 32;
        int grp = j >> 1, hi = j & 1;
        int base = grp * 16 + hi * 8;
        float4 w0 = *(const float4*)(nw + base);
        float4 w1 = *(const float4*)(nw + base + 4);
        float wv[8] = {w0.x, w0.y, w0.z, w0.w, w1.x, w1.y, w1.z, w1.w};
        const uint32_t* u = (const uint32_t*)&raw[i];
        #pragma unroll
        for (int m = 0; m < 4; m++) {
            float2 f = unpack_h2(u[m]);
            uint32_t pk = pack_h2(f.x * rms * wv[2*m], f.y * rms * wv[2*m+1]);
            *(uint32_t*)&dst[grp * 16 + hi * 2 + 4 * m] = pk;
        }
    }
}

// ---------------------------------------------------------------------------
// Output projection, fp16 mma, cp.async double-buffered raw copies.
// ---------------------------------------------------------------------------
__global__ __launch_bounds__(256) void proj_mma_kernel(const float* __restrict__ bias,
                                                       float* __restrict__ out)
{
    extern __shared__ __align__(16) __half qsm[];
    const int A0 = 0, B0 = 12288;

    const int tid  = threadIdx.x;
    const int lane = tid & 31, warp = tid >> 5;
    const int g = lane >> 2, tig = lane & 3;
    const int wm = warp >> 1, wn = warp & 1;
    const int m0 = blockIdx.y * 128, n0 = blockIdx.x * 128;

    const __half* Ab = g_xnh + (size_t)m0 * EMB;
    const __half* Bb = g_wpt + (size_t)n0 * EMB;

    const uint32_t smb = (uint32_t)__cvta_generic_to_shared(qsm);

    auto prefetch = [&](int c, int buf) {
        #pragma unroll
        for (int it = 0; it < 2; it++) {
            int idx = tid + it * 256;
            int row = idx >> 2, cc = idx & 3;
            CP16(smb + (uint32_t)(A0 + buf * 6144 + row * 48 + cc * 8) * 2,
                 Ab + (size_t)row * EMB + c * 32 + cc * 8);
            CP16(smb + (uint32_t)(B0 + buf * 6144 + row * 48 + cc * 8) * 2,
                 Bb + (size_t)row * EMB + c * 32 + cc * 8);
        }
        CPCOMMIT();
    };

    prefetch(0, 0);

    float acc[2][8][4] = {};

    const int NC = EMB / 32;
    for (int c = 0; c < NC; c++) {
        const int cur = c & 1;
        const bool more = (c + 1 < NC);
        if (more) {
            prefetch(c + 1, cur ^ 1);
            asm volatile("cp.async.wait_group 1;");
        } else {
            asm volatile("cp.async.wait_group 0;");
        }
        __syncthreads();

        const int Ac = A0 + cur * 6144;
        const int Bc = B0 + cur * 6144;
        #pragma unroll
        for (int s = 0; s < 2; s++) {
            uint32_t a[2][4];
            #pragma unroll
            for (int mt = 0; mt < 2; mt++) {
                int row = 32 * wm + 16 * mt;
                uint2 u = *(uint2*)&qsm[Ac + (row + g)     * 48 + 16 * s + 4 * tig];
                uint2 v = *(uint2*)&qsm[Ac + (row + g + 8) * 48 + 16 * s + 4 * tig];
                a[mt][0] = u.x; a[mt][1] = v.x; a[mt][2] = u.y; a[mt][3] = v.y;
            }
            #pragma unroll
            for (int t = 0; t < 8; t++) {
                uint2 bb = *(uint2*)&qsm[Bc + (64 * wn + 8 * t + g) * 48 + 16 * s + 4 * tig];
                mma16(acc[0][t], a[0], bb.x, bb.y);
                mma16(acc[1][t], a[1], bb.x, bb.y);
            }
        }
        __syncthreads();
    }

    #pragma unroll
    for (int mt = 0; mt < 2; mt++) {
        int row0 = m0 + 32 * wm + 16 * mt + g;
        #pragma unroll
        for (int t = 0; t < 8; t++) {
            int c = n0 + 64 * wn + 8 * t + 2 * tig;
            float2 r0 = make_float2(acc[mt][t][0] + bias[c], acc[mt][t][1] + bias[c + 1]);
            float2 r1 = make_float2(acc[mt][t][2] + bias[c], acc[mt][t][3] + bias[c + 1]);
            *(float2*)&out[(size_t)row0 * EMB + c]       = r0;
            *(float2*)&out[(size_t)(row0 + 8) * EMB + c] = r1;
        }
    }
}

extern "C" void kernel_launch(void* const* d_in, const int* in_sizes, int n_in,
                              void* d_out, int out_size)
{
    const float* x  = (const float*)d_in[0];
    const float* W1 = (const float*)d_in[1];
    const float* W2 = (const float*)d_in[2];
    const float* Wp = (const float*)d_in[3];
    const float* bp = (const float*)d_in[4];
    const float* nw = (const float*)d_in[5];
    const float* l1 = (const float*)d_in[6];
    const float* l2 = (const float*)d_in[7];
    // d_in[8] = xpos (int64) unused: attention is non-causal in the reference
    float* out = (float*)d_out;

    __half *w1t_p, *w2t_p, *wpt_p;
    cudaGetSymbolAddress((void**)&w1t_p, g_w1t);
    cudaGetSymbolAddress((void**)&w2t_p, g_w2t);
    cudaGetSymbolAddress((void**)&wpt_p, g_wpt);

    convx_kernel<<<768, 256>>>(x);
    convw_kernel<<<dim3(36, 12), 256>>>(W1, w1t_p, 2304);
    convw_kernel<<<dim3(24, 12), 256>>>(W2, w2t_p, 2304);
    convw_kernel<<<dim3(12, 12), 256>>>(Wp, wpt_p, EMB);

    cudaFuncSetAttribute(qkv_mma_kernel, cudaFuncAttributeMaxDynamicSharedMemorySize, 49152);
    qkv_mma_kernel<<<dim3(30, 32), 256, 49152>>>();

    const size_t smem = 56320u * 2;   // 112640 B
    cudaFuncSetAttribute(diff_attn_fp16, cudaFuncAttributeMaxDynamicSharedMemorySize, (int)smem);
    diff_attn_fp16<<<148, 512, smem>>>(l1, l2);   // persistent: 384 jobs / 148 CTAs

    rms_kernel<<<ROWS / 8, 256>>>(nw);

    cudaFuncSetAttribute(proj_mma_kernel, cudaFuncAttributeMaxDynamicSharedMemorySize, 49152);
    proj_mma_kernel<<<dim3(EMB / 128, ROWS / 128), 256, 49152>>>(bp, out);
}

// round 16
// speedup vs baseline: 1.1435x; 1.1435x over previous
#include <cuda_runtime.h>
#include <cuda_fp16.h>
#include <math.h>
#include <stdint.h>

#define BSZ 2
#define SEQ 2048
#define EMB 768
#define NH 12
#define HDIM 64
#define ROWS (BSZ*SEQ)

// fp16 operands. "permuted": within each 16-group, logical (2i,2i+1,2i+8,2i+9)
// stored at phys 4i..4i+3 (so an mma fragment pair is one 8-byte load).
__device__ __half g_xh[ROWS*EMB];          // X, fp16, permuted k-groups
__device__ __half g_w1t[2304*EMB];         // W1^T  [n][k-perm]
__device__ __half g_w2t[1536*EMB];         // W2^T (first 1536 cols; v2 dead)
__device__ __half g_wpt[EMB*EMB];          // Wp^T  [n][k-perm]
__device__ __half g_q1h[BSZ*NH*SEQ*HDIM];  // [B*H][seq][d-perm]
__device__ __half g_k1h[BSZ*NH*SEQ*HDIM];
__device__ __half g_vth[BSZ*NH*SEQ*HDIM];  // V^T [B*H][d][seq-perm]
__device__ __half g_q2h[BSZ*NH*SEQ*HDIM];
__device__ __half g_k2h[BSZ*NH*SEQ*HDIM];
__device__ __half g_atth[ROWS*EMB];        // attention output, fp16
__device__ __half g_xnh[ROWS*EMB];         // rms*nw-scaled, fp16, permuted

// ---------------------------------------------------------------------------
__device__ __forceinline__ float ex2f(float x) {
    float y;
    asm("ex2.approx.f32 %0, %1;" : "=f"(y) : "f"(x));
    return y;
}
__device__ __forceinline__ void mma16(float* c, const uint32_t* a, uint32_t b0, uint32_t b1) {
    asm volatile(
        "mma.sync.aligned.m16n8k16.row.col.f32.f16.f16.f32 "
        "{%0,%1,%2,%3},{%4,%5,%6,%7},{%8,%9},{%0,%1,%2,%3};"
        : "+f"(c[0]), "+f"(c[1]), "+f"(c[2]), "+f"(c[3])
        : "r"(a[0]), "r"(a[1]), "r"(a[2]), "r"(a[3]), "r"(b0), "r"(b1));
}
__device__ __forceinline__ uint32_t pack_h2(float lo, float hi) {
    __half2 h = __float22half2_rn(make_float2(lo, hi));
    return *(uint32_t*)&h;
}
__device__ __forceinline__ float2 unpack_h2(uint32_t u) {
    return __half22float2(*(__half2*)&u);
}
#define CP16(dst_u32, src_ptr) \
    asm volatile("cp.async.cg.shared.global [%0], [%1], 16;" :: "r"(dst_u32), "l"(src_ptr))
#define CPCOMMIT() asm volatile("cp.async.commit_group;")

// 0.125 * log2(e): fold head-dim scale AND exp->exp2 conversion into Q
#define QSCALE 0.18033688011112042f

// ---------------------------------------------------------------------------
// X -> fp16 permuted (row layout preserved). One 16-group per thread.
// ---------------------------------------------------------------------------
__global__ __launch_bounds__(256) void convx_kernel(const float* __restrict__ X)
{
    size_t gidx = (size_t)blockIdx.x * 256 + threadIdx.x;
    const float* src = X + gidx * 16;
    float f[16];
    #pragma unroll
    for (int i = 0; i < 4; i++) {
        float4 v = *(const float4*)(src + 4 * i);
        f[4*i] = v.x; f[4*i+1] = v.y; f[4*i+2] = v.z; f[4*i+3] = v.w;
    }
    uint32_t w8[8];
    #pragma unroll
    for (int i = 0; i < 4; i++) {
        w8[2*i]   = pack_h2(f[2*i],     f[2*i+1]);
        w8[2*i+1] = pack_h2(f[2*i+8],   f[2*i+9]);
    }
    __half* dst = g_xh + gidx * 16;
    *(uint4*)dst       = make_uint4(w8[0], w8[1], w8[2], w8[3]);
    *(uint4*)(dst + 8) = make_uint4(w8[4], w8[5], w8[6], w8[7]);
}

// ---------------------------------------------------------------------------
// Merged weight transpose: W [768 x ncols] f32 -> Wt [ncols][768] fp16 perm.
// blockIdx.z selects {W1, W2, Wp}; excess x-tiles return early.
// ---------------------------------------------------------------------------
__global__ __launch_bounds__(256) void convw_kernel(const float* __restrict__ W1,
                                                    const float* __restrict__ W2,
                                                    const float* __restrict__ Wp,
                                                    __half* __restrict__ w1t,
                                                    __half* __restrict__ w2t,
                                                    __half* __restrict__ wpt)
{
    const int z = blockIdx.z;
    const float* W;
    __half* Wt;
    int stride, ntiles;
    if (z == 0)      { W = W1; Wt = w1t; stride = 2304; ntiles = 36; }
    else if (z == 1) { W = W2; Wt = w2t; stride = 2304; ntiles = 24; }
    else             { W = Wp; Wt = wpt; stride = EMB;  ntiles = 12; }
    if (blockIdx.x >= ntiles) return;

    __shared__ float ts[64][65];
    const int nt = blockIdx.x * 64;
    const int kt = blockIdx.y * 64;
    const int tid = threadIdx.x;

    #pragma unroll
    for (int it = 0; it < 4; it++) {
        int idx = tid + it * 256;
        int krow = idx >> 4, nc = (idx & 15) * 4;
        float4 v = *(const float4*)(W + (size_t)(kt + krow) * stride + nt + nc);
        ts[krow][nc] = v.x; ts[krow][nc+1] = v.y; ts[krow][nc+2] = v.z; ts[krow][nc+3] = v.w;
    }
    __syncthreads();

    int n = tid >> 2, grp = tid & 3;
    int kb = grp * 16;
    uint32_t w8[8];
    #pragma unroll
    for (int i = 0; i < 4; i++) {
        w8[2*i]   = pack_h2(ts[kb + 2*i][n],     ts[kb + 2*i + 1][n]);
        w8[2*i+1] = pack_h2(ts[kb + 2*i + 8][n], ts[kb + 2*i + 9][n]);
    }
    __half* dst = Wt + (size_t)(nt + n) * EMB + kt + kb;
    *(uint4*)dst       = make_uint4(w8[0], w8[1], w8[2], w8[3]);
    *(uint4*)(dst + 8) = make_uint4(w8[4], w8[5], w8[6], w8[7]);
}

// ---------------------------------------------------------------------------
// Merged QKV projection GEMM, fp16 m16n8k16, cp.async double-buffered raw
// copies of pre-converted operands. grid (30, 32): bx<18 -> W1t, else W2t.
// ---------------------------------------------------------------------------
__global__ __launch_bounds__(256) void qkv_mma_kernel()
{
    extern __shared__ __align__(16) __half qsm[];
    const int A0 = 0, B0 = 12288;

    const int tid  = threadIdx.x;
    const int lane = tid & 31, warp = tid >> 5;
    const int g = lane >> 2, tig = lane & 3;
    const int wm = warp >> 1, wn = warp & 1;
    const int m0 = blockIdx.y * 128;
    const bool second = blockIdx.x >= 18;
    const int n0 = (second ? blockIdx.x - 18 : blockIdx.x) * 128;

    const __half* Ab = g_xh + (size_t)m0 * EMB;
    const __half* Bb = second ? g_w2t + (size_t)n0 * EMB
                              : g_w1t + (size_t)n0 * EMB;

    const uint32_t smb = (uint32_t)__cvta_generic_to_shared(qsm);

    auto prefetch = [&](int c, int buf) {
        #pragma unroll
        for (int it = 0; it < 2; it++) {
            int idx = tid + it * 256;
            int row = idx >> 2, cc = idx & 3;
            CP16(smb + (uint32_t)(A0 + buf * 6144 + row * 48 + cc * 8) * 2,
                 Ab + (size_t)row * EMB + c * 32 + cc * 8);
            CP16(smb + (uint32_t)(B0 + buf * 6144 + row * 48 + cc * 8) * 2,
                 Bb + (size_t)row * EMB + c * 32 + cc * 8);
        }
        CPCOMMIT();
    };

    prefetch(0, 0);

    float acc[2][8][4] = {};

    const int NC = EMB / 32;   // 24
    for (int c = 0; c < NC; c++) {
        const int cur = c & 1;
        const bool more = (c + 1 < NC);
        if (more) {
            prefetch(c + 1, cur ^ 1);
            asm volatile("cp.async.wait_group 1;");
        } else {
            asm volatile("cp.async.wait_group 0;");
        }
        __syncthreads();

        const int Ac = A0 + cur * 6144;
        const int Bc = B0 + cur * 6144;
        #pragma unroll
        for (int s = 0; s < 2; s++) {
            uint32_t a[2][4];
            #pragma unroll
            for (int mt = 0; mt < 2; mt++) {
                int row = 32 * wm + 16 * mt;
                uint2 u = *(uint2*)&qsm[Ac + (row + g)     * 48 + 16 * s + 4 * tig];
                uint2 v = *(uint2*)&qsm[Ac + (row + g + 8) * 48 + 16 * s + 4 * tig];
                a[mt][0] = u.x; a[mt][1] = v.x; a[mt][2] = u.y; a[mt][3] = v.y;
            }
            #pragma unroll
            for (int t = 0; t < 8; t++) {
                uint2 bb = *(uint2*)&qsm[Bc + (64 * wn + 8 * t + g) * 48 + 16 * s + 4 * tig];
                mma16(acc[0][t], a[0], bb.x, bb.y);
                mma16(acc[1][t], a[1], bb.x, bb.y);
            }
        }
        __syncthreads();
    }

    const int cbase = n0 + 64 * wn;
    const int sel = cbase / EMB;
    const int h = (cbase - sel * EMB) >> 6;
    const int bb = m0 >> 11;

    if (!second && sel == 2) {
        __half* vt = g_vth + (size_t)(bb * NH + h) * HDIM * SEQ;
        #pragma unroll
        for (int mt = 0; mt < 2; mt++) {
            int rb = (m0 & (SEQ - 1)) + 32 * wm + 16 * mt;
            int n1p = rb + 4 * (g >> 1) + (g & 1);
            #pragma unroll
            for (int t = 0; t < 8; t++) {
                int d0 = 8 * t + 2 * tig;
                vt[(size_t)d0 * SEQ + n1p]           = __float2half_rn(acc[mt][t][0]);
                vt[(size_t)(d0 + 1) * SEQ + n1p]     = __float2half_rn(acc[mt][t][1]);
                vt[(size_t)d0 * SEQ + n1p + 2]       = __float2half_rn(acc[mt][t][2]);
                vt[(size_t)(d0 + 1) * SEQ + n1p + 2] = __float2half_rn(acc[mt][t][3]);
            }
        }
    } else {
        __half* dst = second ? (sel == 0 ? g_q2h : g_k2h)
                             : (sel == 0 ? g_q1h : g_k1h);
        const float scl = (sel == 0) ? QSCALE : 1.0f;
        #pragma unroll
        for (int mt = 0; mt < 2; mt++) {
            int n = (m0 + 32 * wm + 16 * mt + g) & (SEQ - 1);
            size_t base = (size_t)(bb * NH + h) * SEQ;
            #pragma unroll
            for (int t = 0; t < 8; t++) {
                int dphys = 16 * (t >> 1) + 4 * tig + 2 * (t & 1);
                *(uint32_t*)&dst[(base + n) * HDIM + dphys] =
                    pack_h2(acc[mt][t][0] * scl, acc[mt][t][1] * scl);
                *(uint32_t*)&dst[(base + n + 8) * HDIM + dphys] =
                    pack_h2(acc[mt][t][2] * scl, acc[mt][t][3] * scl);
            }
        }
    }
}

// ---------------------------------------------------------------------------
// Differential flash attention, fp16 mma, 512 threads (16 warps), k-split.
// 3-stage cp.async pipeline; K1+K2+V committed as ONE group per k-tile:
//   wait(<=2 pending) -> sync -> compute S+softmax+PV -> sync -> prefetch(kt+3)
// smem (halfs): Q2 0 (10240), K1 10240 (3x5120), K2 25600, V 40960. 112640 B.
// ---------------------------------------------------------------------------
__global__ __launch_bounds__(512) void diff_attn_fp16(const float* __restrict__ lam1,
                                                      const float* __restrict__ lam2)
{
    extern __shared__ __align__(16) char smraw[];
    __half* smh = (__half*)smraw;
    const int Q2H = 0, K1H = 10240, K2H = 25600, VH = 40960;

    const int tid  = threadIdx.x;
    const int lane = tid & 31, warp = tid >> 5;
    const int g = lane >> 2, tig = lane & 3;
    const int qg = warp & 7, kh = warp >> 3;
    const int r = 16 * qg;
    const int bh = blockIdx.y;
    const int b = bh / NH, h = bh - b * NH;
    const int q0 = blockIdx.x * 128;

    const __half* Q1g = g_q1h + ((size_t)bh * SEQ + q0) * HDIM;
    const __half* Q2g = g_q2h + ((size_t)bh * SEQ + q0) * HDIM;
    const __half* K1g = g_k1h + (size_t)bh * SEQ * HDIM;
    const __half* K2g = g_k2h + (size_t)bh * SEQ * HDIM;
    const __half* Vtg = g_vth + (size_t)bh * HDIM * SEQ;

    #pragma unroll
    for (int it = 0; it < 2; it++) {
        int i = tid + it * 512;
        int row = i >> 3, c = i & 7;
        *(uint4*)&smh[Q2H + row * 80 + c * 8] = *(const uint4*)(Q2g + row * 64 + c * 8);
    }
    uint32_t q1f[4][4];
    #pragma unroll
    for (int s = 0; s < 4; s++) {
        uint2 u = *(const uint2*)(Q1g + (r + g)     * 64 + 16 * s + 4 * tig);
        uint2 v = *(const uint2*)(Q1g + (r + g + 8) * 64 + 16 * s + 4 * tig);
        q1f[s][0] = u.x; q1f[s][1] = v.x; q1f[s][2] = u.y; q1f[s][3] = v.y;
    }

    const uint32_t smb = (uint32_t)__cvta_generic_to_shared(smraw);

    auto prefetch_all = [&](int kt, int buf) {
        int row = tid >> 3, c = tid & 7;
        CP16(smb + (uint32_t)(K1H + buf * 5120 + row * 80 + c * 8) * 2,
             K1g + (size_t)kt * 4096 + row * 64 + c * 8);
        CP16(smb + (uint32_t)(K2H + buf * 5120 + row * 80 + c * 8) * 2,
             K2g + (size_t)kt * 4096 + row * 64 + c * 8);
        CP16(smb + (uint32_t)(VH + buf * 5120 + row * 80 + c * 8) * 2,
             Vtg + (size_t)row * SEQ + kt * 64 + c * 8);
        CPCOMMIT();
    };

    const int NT = SEQ / 64;   // 32
    prefetch_all(0, 0);
    prefetch_all(1, 1);
    prefetch_all(2, 2);

    float o1[8][4] = {}, o2[8][4] = {};
    float l1[2] = {0.f, 0.f}, l2[2] = {0.f, 0.f};

    for (int kt = 0; kt < NT; kt++) {
        const int buf = kt % 3;
        const int pa = NT - kt - 1;
        if (pa >= 2)      asm volatile("cp.async.wait_group 2;");
        else if (pa == 1) asm volatile("cp.async.wait_group 1;");
        else              asm volatile("cp.async.wait_group 0;");
        __syncthreads();

        const int K1c = K1H + buf * 5120;
        const int K2c = K2H + buf * 5120;
        const int Vc  = VH  + buf * 5120;

        uint32_t pa1[2][4], pa2[2][4];
        // ---- merged S phase: two independent LDS->mma chains ----
        {
            float s1[4][4] = {}, s2[4][4] = {};
            #pragma unroll
            for (int s = 0; s < 4; s++) {
                uint32_t aq[4];
                uint2 u = *(uint2*)&smh[Q2H + (r + g)     * 80 + 16 * s + 4 * tig];
                uint2 v = *(uint2*)&smh[Q2H + (r + g + 8) * 80 + 16 * s + 4 * tig];
                aq[0] = u.x; aq[1] = v.x; aq[2] = u.y; aq[3] = v.y;
                #pragma unroll
                for (int t = 0; t < 4; t++) {
                    int kr = 32 * kh + 8 * t + g;
                    uint2 k1 = *(uint2*)&smh[K1c + kr * 80 + 16 * s + 4 * tig];
                    uint2 k2 = *(uint2*)&smh[K2c + kr * 80 + 16 * s + 4 * tig];
                    mma16(s1[t], q1f[s], k1.x, k1.y);
                    mma16(s2[t], aq,     k2.x, k2.y);
                }
            }
            #pragma unroll
            for (int t = 0; t < 4; t++) {
                float a0 = ex2f(s1[t][0]);
                float a1 = ex2f(s1[t][1]);
                float a2 = ex2f(s1[t][2]);
                float a3 = ex2f(s1[t][3]);
                l1[0] += a0 + a1;
                l1[1] += a2 + a3;
                pa1[t >> 1][2 * (t & 1)]     = pack_h2(a0, a1);
                pa1[t >> 1][2 * (t & 1) + 1] = pack_h2(a2, a3);
                float b0 = ex2f(s2[t][0]);
                float b1 = ex2f(s2[t][1]);
                float b2 = ex2f(s2[t][2]);
                float b3 = ex2f(s2[t][3]);
                l2[0] += b0 + b1;
                l2[1] += b2 + b3;
                pa2[t >> 1][2 * (t & 1)]     = pack_h2(b0, b1);
                pa2[t >> 1][2 * (t & 1) + 1] = pack_h2(b2, b3);
            }
        }

        // ---- O += P @ V (V already resident — same commit group as K) ----
        #pragma unroll
        for (int s2i = 0; s2i < 2; s2i++) {
            #pragma unroll
            for (int t = 0; t < 8; t++) {
                int vr = 8 * t + g;
                uint2 vb = *(uint2*)&smh[Vc + vr * 80 + 32 * kh + 16 * s2i + 4 * tig];
                mma16(o1[t], pa1[s2i], vb.x, vb.y);
                mma16(o2[t], pa2[s2i], vb.x, vb.y);
            }
        }
        __syncthreads();

        if (kt + 3 < NT) prefetch_all(kt + 3, buf);
    }

    // ---- final reduction across tig lanes (l) and kh warp pairs (l, O) ----
    #pragma unroll
    for (int rr = 0; rr < 2; rr++) {
        l1[rr] += __shfl_xor_sync(0xffffffffu, l1[rr], 1);
        l1[rr] += __shfl_xor_sync(0xffffffffu, l1[rr], 2);
        l2[rr] += __shfl_xor_sync(0xffffffffu, l2[rr], 1);
        l2[rr] += __shfl_xor_sync(0xffffffffu, l2[rr], 2);
    }
    float* ob1 = (float*)smraw;          // 128x68 f32
    float* ob2 = ob1 + 8704;
    float* lbuf = ob2 + 8704;            // 256 f32
    if (kh == 1) {
        #pragma unroll
        for (int t = 0; t < 8; t++) {
            *(float2*)&ob1[(r + g)     * 68 + 8 * t + 2 * tig] = make_float2(o1[t][0], o1[t][1]);
            *(float2*)&ob1[(r + g + 8) * 68 + 8 * t + 2 * tig] = make_float2(o1[t][2], o1[t][3]);
            *(float2*)&ob2[(r + g)     * 68 + 8 * t + 2 * tig] = make_float2(o2[t][0], o2[t][1]);
            *(float2*)&ob2[(r + g + 8) * 68 + 8 * t + 2 * tig] = make_float2(o2[t][2], o2[t][3]);
        }
        if (tig == 0) {
            lbuf[r + g]           = l1[0];
            lbuf[r + g + 8]       = l1[1];
            lbuf[128 + r + g]     = l2[0];
            lbuf[128 + r + g + 8] = l2[1];
        }
    }
    __syncthreads();
    if (kh == 0) {
        const float lam = lam1[h] - lam2[h] + 0.1f;
        const float i10 = 1.f / (l1[0] + lbuf[r + g]);
        const float i11 = 1.f / (l1[1] + lbuf[r + g + 8]);
        const float i20 = 1.f / (l2[0] + lbuf[128 + r + g]);
        const float i21 = 1.f / (l2[1] + lbuf[128 + r + g + 8]);
        const int n = q0 + r + g;
        #pragma unroll
        for (int t = 0; t < 8; t++) {
            const int col = h * HDIM + 8 * t + 2 * tig;
            float2 p10 = *(float2*)&ob1[(r + g)     * 68 + 8 * t + 2 * tig];
            float2 p11 = *(float2*)&ob1[(r + g + 8) * 68 + 8 * t + 2 * tig];
            float2 p20 = *(float2*)&ob2[(r + g)     * 68 + 8 * t + 2 * tig];
            float2 p21 = *(float2*)&ob2[(r + g + 8) * 68 + 8 * t + 2 * tig];
            *(uint32_t*)&g_atth[((size_t)(b * SEQ + n)) * EMB + col] =
                pack_h2((o1[t][0] + p10.x) * i10 - lam * (o2[t][0] + p20.x) * i20,
                        (o1[t][1] + p10.y) * i10 - lam * (o2[t][1] + p20.y) * i20);
            *(uint32_t*)&g_atth[((size_t)(b * SEQ + n + 8)) * EMB + col] =
                pack_h2((o1[t][2] + p11.x) * i11 - lam * (o2[t][2] + p21.x) * i21,
                        (o1[t][3] + p11.y) * i11 - lam * (o2[t][3] + p21.y) * i21);
        }
    }
}

// ---------------------------------------------------------------------------
// RMSNorm + scale + permute: g_xnh = fp16_perm(g_atth * rms * nw).
// ---------------------------------------------------------------------------
__global__ __launch_bounds__(256) void rms_kernel(const float* __restrict__ nw)
{
    const int lane = threadIdx.x & 31, warp = threadIdx.x >> 5;
    const int row = blockIdx.x * 8 + warp;
    const __half* p = g_atth + (size_t)row * EMB;

    uint4 raw[3];
    float ss = 0.f;
    #pragma unroll
    for (int i = 0; i < 3; i++) {
        raw[i] = *(const uint4*)(p + lane * 8 + i * 256);
        const uint32_t* u = (const uint32_t*)&raw[i];
        #pragma unroll
        for (int m = 0; m < 4; m++) {
            float2 f = unpack_h2(u[m]);
            ss += f.x * f.x + f.y * f.y;
        }
    }
    #pragma unroll
    for (int off = 16; off > 0; off >>= 1)
        ss += __shfl_xor_sync(0xffffffffu, ss, off);
    const float rms = rsqrtf(ss * (1.0f / EMB) + 1e-6f);

    __half* dst = g_xnh + (size_t)row * EMB;
    #pragma unroll
    for (int i = 0; i < 3; i++) {
        int j = lane + i * 32;
        int grp = j >> 1, hi = j & 1;
        int base = grp * 16 + hi * 8;
        float4 w0 = *(const float4*)(nw + base);
        float4 w1 = *(const float4*)(nw + base + 4);
        float wv[8] = {w0.x, w0.y, w0.z, w0.w, w1.x, w1.y, w1.z, w1.w};
        const uint32_t* u = (const uint32_t*)&raw[i];
        #pragma unroll
        for (int m = 0; m < 4; m++) {
            float2 f = unpack_h2(u[m]);
            uint32_t pk = pack_h2(f.x * rms * wv[2*m], f.y * rms * wv[2*m+1]);
            *(uint32_t*)&dst[grp * 16 + hi * 2 + 4 * m] = pk;
        }
    }
}

// ---------------------------------------------------------------------------
// Output projection, fp16 mma, cp.async double-buffered raw copies.
// ---------------------------------------------------------------------------
__global__ __launch_bounds__(256) void proj_mma_kernel(const float* __restrict__ bias,
                                                       float* __restrict__ out)
{
    extern __shared__ __align__(16) __half qsm[];
    const int A0 = 0, B0 = 12288;

    const int tid  = threadIdx.x;
    const int lane = tid & 31, warp = tid >> 5;
    const int g = lane >> 2, tig = lane & 3;
    const int wm = warp >> 1, wn = warp & 1;
    const int m0 = blockIdx.y * 128, n0 = blockIdx.x * 128;

    const __half* Ab = g_xnh + (size_t)m0 * EMB;
    const __half* Bb = g_wpt + (size_t)n0 * EMB;

    const uint32_t smb = (uint32_t)__cvta_generic_to_shared(qsm);

    auto prefetch = [&](int c, int buf) {
        #pragma unroll
        for (int it = 0; it < 2; it++) {
            int idx = tid + it * 256;
            int row = idx >> 2, cc = idx & 3;
            CP16(smb + (uint32_t)(A0 + buf * 6144 + row * 48 + cc * 8) * 2,
                 Ab + (size_t)row * EMB + c * 32 + cc * 8);
            CP16(smb + (uint32_t)(B0 + buf * 6144 + row * 48 + cc * 8) * 2,
                 Bb + (size_t)row * EMB + c * 32 + cc * 8);
        }
        CPCOMMIT();
    };

    prefetch(0, 0);

    float acc[2][8][4] = {};

    const int NC = EMB / 32;
    for (int c = 0; c < NC; c++) {
        const int cur = c & 1;
        const bool more = (c + 1 < NC);
        if (more) {
            prefetch(c + 1, cur ^ 1);
            asm volatile("cp.async.wait_group 1;");
        } else {
            asm volatile("cp.async.wait_group 0;");
        }
        __syncthreads();

        const int Ac = A0 + cur * 6144;
        const int Bc = B0 + cur * 6144;
        #pragma unroll
        for (int s = 0; s < 2; s++) {
            uint32_t a[2][4];
            #pragma unroll
            for (int mt = 0; mt < 2; mt++) {
                int row = 32 * wm + 16 * mt;
                uint2 u = *(uint2*)&qsm[Ac + (row + g)     * 48 + 16 * s + 4 * tig];
                uint2 v = *(uint2*)&qsm[Ac + (row + g + 8) * 48 + 16 * s + 4 * tig];
                a[mt][0] = u.x; a[mt][1] = v.x; a[mt][2] = u.y; a[mt][3] = v.y;
            }
            #pragma unroll
            for (int t = 0; t < 8; t++) {
                uint2 bb = *(uint2*)&qsm[Bc + (64 * wn + 8 * t + g) * 48 + 16 * s + 4 * tig];
                mma16(acc[0][t], a[0], bb.x, bb.y);
                mma16(acc[1][t], a[1], bb.x, bb.y);
            }
        }
        __syncthreads();
    }

    #pragma unroll
    for (int mt = 0; mt < 2; mt++) {
        int row0 = m0 + 32 * wm + 16 * mt + g;
        #pragma unroll
        for (int t = 0; t < 8; t++) {
            int c = n0 + 64 * wn + 8 * t + 2 * tig;
            float2 r0 = make_float2(acc[mt][t][0] + bias[c], acc[mt][t][1] + bias[c + 1]);
            float2 r1 = make_float2(acc[mt][t][2] + bias[c], acc[mt][t][3] + bias[c + 1]);
            *(float2*)&out[(size_t)row0 * EMB + c]       = r0;
            *(float2*)&out[(size_t)(row0 + 8) * EMB + c] = r1;
        }
    }
}

extern "C" void kernel_launch(void* const* d_in, const int* in_sizes, int n_in,
                              void* d_out, int out_size)
{
    const float* x  = (const float*)d_in[0];
    const float* W1 = (const float*)d_in[1];
    const float* W2 = (const float*)d_in[2];
    const float* Wp = (const float*)d_in[3];
    const float* bp = (const float*)d_in[4];
    const float* nw = (const float*)d_in[5];
    const float* l1 = (const float*)d_in[6];
    const float* l2 = (const float*)d_in[7];
    // d_in[8] = xpos (int64) unused: attention is non-causal in the reference
    float* out = (float*)d_out;

    __half *w1t_p, *w2t_p, *wpt_p;
    cudaGetSymbolAddress((void**)&w1t_p, g_w1t);
    cudaGetSymbolAddress((void**)&w2t_p, g_w2t);
    cudaGetSymbolAddress((void**)&wpt_p, g_wpt);

    convx_kernel<<<768, 256>>>(x);
    convw_kernel<<<dim3(36, 12, 3), 256>>>(W1, W2, Wp, w1t_p, w2t_p, wpt_p);

    cudaFuncSetAttribute(qkv_mma_kernel, cudaFuncAttributeMaxDynamicSharedMemorySize, 49152);
    qkv_mma_kernel<<<dim3(30, 32), 256, 49152>>>();

    const size_t smem = 56320u * 2;   // 112640 B
    cudaFuncSetAttribute(diff_attn_fp16, cudaFuncAttributeMaxDynamicSharedMemorySize, (int)smem);
    diff_attn_fp16<<<dim3(SEQ / 128, BSZ * NH), 512, smem>>>(l1, l2);

    rms_kernel<<<ROWS / 8, 256>>>(nw);

    cudaFuncSetAttribute(proj_mma_kernel, cudaFuncAttributeMaxDynamicSharedMemorySize, 49152);
    proj_mma_kernel<<<dim3(EMB / 128, ROWS / 128), 256, 49152>>>(bp, out);
}